// round 10
// baseline (speedup 1.0000x reference)
#include <cuda_runtime.h>

#define Wd 256
#define Hd 256
#define Bd 64
#define NPIX (Bd*Hd*Wd)
#define HIMG 32
#define HPIX (HIMG*Hd*Wd)
#define NVH  (HPIX/4)
#define TX 64
#define TY 16
#define SS 68              // smem row stride (floats): 17 vecs
#define EPSf 1e-12f

// ---- iteration-invariant scratch ----
__device__ __align__(16) float g_g2x[NPIX];
__device__ __align__(16) float g_g2y[NPIX];
__device__ __align__(16) float g_rc [NPIX];
// ---- double-buffered dual state ----
__device__ __align__(16) float g_p11[2][NPIX];
__device__ __align__(16) float g_p12[2][NPIX];
__device__ __align__(16) float g_p21[2][NPIX];
__device__ __align__(16) float g_p22[2][NPIX];
// ---- u scratch (ping-pongs with d_out) ----
__device__ __align__(16) float g_u1s[NPIX];
__device__ __align__(16) float g_u2s[NPIX];

union F4 { float4 v; float f[4]; };
__device__ __forceinline__ float4 ld4(const float* p) { return *reinterpret_cast<const float4*>(p); }
__device__ __forceinline__ void   st4(float* p, float4 v) { *reinterpret_cast<float4*>(p) = v; }
__device__ __forceinline__ F4 zf4() { F4 a; a.v = make_float4(0,0,0,0); return a; }

// u' = u + v(u) + ts*div(p)   (one pixel)
__device__ __forceinline__ void u_lane(
    float u1, float u2, float gx, float gy, float rc,
    float p11, float p11L, float p12, float p12U,
    float p21, float p21L, float p22, float p22U,
    bool j0, bool i0, float ts, float l_t,
    float& o1, float& o2)
{
    float dx1 = j0 ? p11 : (p11 - p11L);
    float dx2 = j0 ? p21 : (p21 - p21L);
    float dy1 = i0 ? p12 : (p12 - p12U);
    float dy2 = i0 ? p22 : (p22 - p22U);
    float rho  = rc + gx * u1 + gy * u2 + EPSf;
    float grad = gx * gx + gy * gy + EPSf;
    float lg   = l_t * grad;
    float v1, v2;
    if      (rho < -lg)   { v1 =  l_t * gx; v2 =  l_t * gy; }
    else if (rho >  lg)   { v1 = -l_t * gx; v2 = -l_t * gy; }
    else if (grad > EPSf) { float s = -rho / grad; v1 = s * gx; v2 = s * gy; }
    else                  { v1 = 0.f; v2 = 0.f; }
    o1 = u1 + v1 + ts * (dx1 + dy1);
    o2 = u2 + v2 + ts * (dx2 + dy2);
}

// p' = (p + taut*grad_u) / (1 + taut*|grad_u|)   (one pixel)
__device__ __forceinline__ void p_lane(
    float uC1, float uR1, float uD1, float uC2, float uR2, float uD2,
    bool hasR, bool hasD, float taut,
    float p11, float p12, float p21, float p22,
    float& o11, float& o12, float& o21, float& o22)
{
    float u1x = hasR ? (uR1 - uC1) : 0.f;
    float u2x = hasR ? (uR2 - uC2) : 0.f;
    float u1y = hasD ? (uD1 - uC1) : 0.f;
    float u2y = hasD ? (uD2 - uC2) : 0.f;
    float n1 = sqrtf(u1x*u1x + u1y*u1y + EPSf);
    float n2 = sqrtf(u2x*u2x + u2y*u2y + EPSf);
    float f1 = 1.0f / (1.0f + taut * n1);
    float f2 = 1.0f / (1.0f + taut * n2);
    o11 = (p11 + taut * u1x) * f1;
    o12 = (p12 + taut * u1y) * f1;
    o21 = (p21 + taut * u2x) * f2;
    o22 = (p22 + taut * u2y) * f2;
}

// ============================================================================
// Init (per half): g2x, g2y (centered grads of y, x boundary), rc = y - x.
// ============================================================================
__global__ void __launch_bounds__(256) k_init(
    const float* __restrict__ x, const float* __restrict__ y, int off)
{
    int v = blockIdx.x * blockDim.x + threadIdx.x;
    if (v >= NVH) return;
    int il = v << 2;
    int idx = il + off;
    int j4 = il & (Wd - 1);
    int i  = (il >> 8) & (Hd - 1);

    F4 X, Y, Yu, Yd, Xu, Xd;
    X.v = ld4(x + idx);
    Y.v = ld4(y + idx);
    float yl = (j4 > 0)       ? y[idx - 1] : 0.f;
    float yr = (j4 + 4 < Wd)  ? y[idx + 4] : 0.f;
    Yu.v = (i > 0)      ? ld4(y + idx - Wd) : make_float4(0,0,0,0);
    Yd.v = (i < Hd - 1) ? ld4(y + idx + Wd) : make_float4(0,0,0,0);
    Xd.v = (i == 0)      ? ld4(x + idx + Wd) : make_float4(0,0,0,0);
    Xu.v = (i == Hd - 1) ? ld4(x + idx - Wd) : make_float4(0,0,0,0);

    F4 GX, GY, RC;
#pragma unroll
    for (int k = 0; k < 4; k++) {
        int j = j4 + k;
        float gx;
        if (j == 0)            gx = 0.5f * (X.f[1] - X.f[0]);
        else if (j == Wd - 1)  gx = 0.5f * (X.f[3] - X.f[2]);
        else {
            float yn = (k < 3) ? Y.f[k + 1] : yr;
            float yp = (k > 0) ? Y.f[k - 1] : yl;
            gx = 0.5f * (yn - yp);
        }
        float gy;
        if (i == 0)            gy = 0.5f * (Xd.f[k] - X.f[k]);
        else if (i == Hd - 1)  gy = 0.5f * (X.f[k] - Xu.f[k]);
        else                   gy = 0.5f * (Yd.f[k] - Yu.f[k]);
        GX.f[k] = gx; GY.f[k] = gy; RC.f[k] = Y.f[k] - X.f[k];
    }
    st4(g_g2x + idx, GX.v);
    st4(g_g2y + idx, GY.v);
    st4(g_rc  + idx, RC.v);
}

// ============================================================================
// Fused iteration k: U_k then P_k. 320 threads; stage 1 covers the full
// 17x17-vec extended tile in ONE shot (no loop); stage 2 p' on center.
// Double-buffered u and p => race-free. FIRST: u=p=0. LAST: stage 2 skipped.
// ============================================================================
template<bool FIRST, bool LAST, int PRD, int PWR>
__global__ void __launch_bounds__(320) k_fused(
    const float* __restrict__ tp, const float* __restrict__ lp,
    const float* __restrict__ ap,
    const float* __restrict__ u1r, const float* __restrict__ u2r,
    float* __restrict__ u1w, float* __restrict__ u2w, int off)
{
    __shared__ __align__(16) float sU1[17*SS], sU2[17*SS];

    const int tid = threadIdx.x;
    const int tx0 = blockIdx.x * TX;
    const int ty0 = blockIdx.y * TY;
    const int base = off + blockIdx.z * (Hd * Wd);

    const float ts   = tp[0];
    const float l_t  = lp[0] * ts;
    const float taut = ap[0] / ts;

    const float* __restrict__ P11r = g_p11[PRD];
    const float* __restrict__ P12r = g_p12[PRD];
    const float* __restrict__ P21r = g_p21[PRD];
    const float* __restrict__ P22r = g_p22[PRD];

    // ---- stage 1: u' on extended region (one task per thread) ----
    if (tid < 17*17) {
        int r = tid / 17, v = tid - r * 17;
        int grow = ty0 + r;
        int gcol = tx0 + 4*v;
        bool valid = (grow < Hd) && (gcol < Wd);

        F4 O1 = zf4(), O2 = zf4();
        if (valid) {
            int o = base + grow * Wd + gcol;
            F4 U1 = zf4(), U2 = zf4();
            F4 Q11 = zf4(), Q12 = zf4(), Q21 = zf4(), Q22 = zf4();
            F4 P12u = zf4(), P22u = zf4();
            float l11 = 0.f, l21 = 0.f;
            if (!FIRST) {
                U1.v = ld4(u1r + o); U2.v = ld4(u2r + o);
                Q11.v = ld4(P11r + o); Q12.v = ld4(P12r + o);
                Q21.v = ld4(P21r + o); Q22.v = ld4(P22r + o);
                if (grow > 0) {
                    P12u.v = ld4(P12r + o - Wd);
                    P22u.v = ld4(P22r + o - Wd);
                }
                if (gcol > 0) { l11 = P11r[o - 1]; l21 = P21r[o - 1]; }
            }
            F4 GX, GY, RC;
            GX.v = ld4(g_g2x + o); GY.v = ld4(g_g2y + o); RC.v = ld4(g_rc + o);

            bool i0 = (grow == 0);
#pragma unroll
            for (int k = 0; k < 4; k++) {
                float pl11 = (k > 0) ? Q11.f[k-1] : l11;
                float pl21 = (k > 0) ? Q21.f[k-1] : l21;
                u_lane(U1.f[k], U2.f[k], GX.f[k], GY.f[k], RC.f[k],
                       Q11.f[k], pl11, Q12.f[k], P12u.f[k],
                       Q21.f[k], pl21, Q22.f[k], P22u.f[k],
                       (gcol + k) == 0, i0, ts, l_t, O1.f[k], O2.f[k]);
            }
            if (r < TY && v < 16) {      // center tile -> global u-out
                st4(u1w + o, O1.v);
                st4(u2w + o, O2.v);
            }
        }
        if (!LAST) {
            st4(sU1 + r*SS + 4*v, O1.v);
            st4(sU2 + r*SS + 4*v, O2.v);
        }
    }

    if (LAST) return;
    __syncthreads();

    // ---- stage 2: p' on center from smem u' ----
    if (tid < 256) {
        int r = tid >> 4, v = tid & 15;
        int grow = ty0 + r;
        int gcol = tx0 + 4*v;
        int o = base + grow * Wd + gcol;
        int s = r*SS + 4*v;

        F4 U1c, U2c, U1d, U2d;
        U1c.v = *(float4*)(sU1 + s);      U2c.v = *(float4*)(sU2 + s);
        U1d.v = *(float4*)(sU1 + s + SS); U2d.v = *(float4*)(sU2 + s + SS);
        float u1R = sU1[s + 4];
        float u2R = sU2[s + 4];

        F4 Q11 = zf4(), Q12 = zf4(), Q21 = zf4(), Q22 = zf4();
        if (!FIRST) {   // reload p_old: L1 hit (this block touched it in stage 1)
            Q11.v = ld4(P11r + o); Q12.v = ld4(P12r + o);
            Q21.v = ld4(P21r + o); Q22.v = ld4(P22r + o);
        }

        bool hasD = (grow < Hd - 1);
        F4 N11, N12, N21, N22;
#pragma unroll
        for (int k = 0; k < 4; k++) {
            int j = gcol + k;
            float uR1 = (k < 3) ? U1c.f[k+1] : u1R;
            float uR2 = (k < 3) ? U2c.f[k+1] : u2R;
            p_lane(U1c.f[k], uR1, U1d.f[k], U2c.f[k], uR2, U2d.f[k],
                   (j < Wd - 1), hasD, taut,
                   Q11.f[k], Q12.f[k], Q21.f[k], Q22.f[k],
                   N11.f[k], N12.f[k], N21.f[k], N22.f[k]);
        }
        st4(g_p11[PWR] + o, N11.v);
        st4(g_p12[PWR] + o, N12.v);
        st4(g_p21[PWR] + o, N21.v);
        st4(g_p22[PWR] + o, N22.v);
    }
}

// ============================================================================
// Schedule per half: init(g); 10 fused iterations.
// u buffers: iter1->S, then ping-pong; iter10 -> d_out.
// p sets:    iter1 w0; iter2 r0 w1; ...; iter9 w0; iter10 r0 (LAST, no write).
// ============================================================================
extern "C" void kernel_launch(void* const* d_in, const int* in_sizes, int n_in,
                              void* d_out, int out_size)
{
    const float* x = (const float*)d_in[0];
    const float* y = (const float*)d_in[1];
    const float* t = (const float*)d_in[8];
    const float* l = (const float*)d_in[9];
    const float* a = (const float*)d_in[10];

    float* ud1 = (float*)d_out;
    float* ud2 = ud1 + NPIX;

    float* us1; cudaGetSymbolAddress((void**)&us1, g_u1s);
    float* us2; cudaGetSymbolAddress((void**)&us2, g_u2s);

    const int blocksI = (NVH + 255) / 256;
    dim3 grid(Wd / TX, Hd / TY, HIMG);

    for (int h = 0; h < 2; ++h) {
        int off = h * HPIX;
        k_init<<<blocksI, 256>>>(x, y, off);
        k_fused<true,  false, 0, 0><<<grid, 320>>>(t, l, a, us1, us2, us1, us2, off); // it1  -> S, p w0
        k_fused<false, false, 0, 1><<<grid, 320>>>(t, l, a, us1, us2, ud1, ud2, off); // it2  S->D, r0 w1
        k_fused<false, false, 1, 0><<<grid, 320>>>(t, l, a, ud1, ud2, us1, us2, off); // it3  D->S, r1 w0
        k_fused<false, false, 0, 1><<<grid, 320>>>(t, l, a, us1, us2, ud1, ud2, off); // it4  S->D
        k_fused<false, false, 1, 0><<<grid, 320>>>(t, l, a, ud1, ud2, us1, us2, off); // it5  D->S
        k_fused<false, false, 0, 1><<<grid, 320>>>(t, l, a, us1, us2, ud1, ud2, off); // it6  S->D
        k_fused<false, false, 1, 0><<<grid, 320>>>(t, l, a, ud1, ud2, us1, us2, off); // it7  D->S
        k_fused<false, false, 0, 1><<<grid, 320>>>(t, l, a, us1, us2, ud1, ud2, off); // it8  S->D
        k_fused<false, false, 1, 0><<<grid, 320>>>(t, l, a, ud1, ud2, us1, us2, off); // it9  D->S, w0
        k_fused<false, true,  0, 0><<<grid, 320>>>(t, l, a, us1, us2, ud1, ud2, off); // it10 S->D (LAST, r0)
    }
}

// round 11
// speedup vs baseline: 1.5461x; 1.5461x over previous
#include <cuda_runtime.h>
#include <cuda_fp16.h>

#define Wd 256
#define Hd 256
#define Bd 64
#define NPIX (Bd*Hd*Wd)
#define HPIX (NPIX/2)      // elements per batch half
#define NVH  (HPIX/4)      // float4 vectors per half
#define EPSf 1e-12f

// ---- iteration-invariant scratch (fp32) ----
__device__ __align__(16) float g_g2x[NPIX];
__device__ __align__(16) float g_g2y[NPIX];
__device__ __align__(16) float g_rc [NPIX];
// ---- dual state in fp16 (hottest traffic; |p| <~ 1) ----
__device__ __align__(16) __half g_p11[NPIX];
__device__ __align__(16) __half g_p12[NPIX];
__device__ __align__(16) __half g_p21[NPIX];
__device__ __align__(16) __half g_p22[NPIX];

union F4 { float4 v; float f[4]; };

__device__ __forceinline__ float4 ld4(const float* p) { return *reinterpret_cast<const float4*>(p); }
__device__ __forceinline__ void   st4(float* p, float4 v) { *reinterpret_cast<float4*>(p) = v; }

// load 4 consecutive halves -> float4 (8B vector load)
__device__ __forceinline__ float4 ldh4(const __half* p) {
    uint2 u = *reinterpret_cast<const uint2*>(p);
    __half2 h01 = *reinterpret_cast<__half2*>(&u.x);
    __half2 h23 = *reinterpret_cast<__half2*>(&u.y);
    float2 a = __half22float2(h01);
    float2 b = __half22float2(h23);
    return make_float4(a.x, a.y, b.x, b.y);
}
// store float4 -> 4 halves (8B vector store, RN)
__device__ __forceinline__ void sth4(__half* p, float4 v) {
    __half2 h01 = __floats2half2_rn(v.x, v.y);
    __half2 h23 = __floats2half2_rn(v.z, v.w);
    uint2 u;
    u.x = *reinterpret_cast<unsigned*>(&h01);
    u.y = *reinterpret_cast<unsigned*>(&h23);
    *reinterpret_cast<uint2*>(p) = u;
}

// ============================================================================
// Init (per half): g2x, g2y, rc = y-x, iteration-1 u (u=0, p=0).
// ============================================================================
__global__ void __launch_bounds__(256) k_init(
    const float* __restrict__ x, const float* __restrict__ y,
    const float* __restrict__ tp, const float* __restrict__ lp,
    float* __restrict__ u1, float* __restrict__ u2, int off)
{
    int v = blockIdx.x * blockDim.x + threadIdx.x;
    if (v >= NVH) return;
    int il = v << 2;
    int idx = il + off;
    int j4 = il & (Wd - 1);
    int i  = (il >> 8) & (Hd - 1);

    float ts  = tp[0];
    float l_t = lp[0] * ts;

    F4 X, Y, Yu, Yd, Xu, Xd;
    X.v = ld4(x + idx);
    Y.v = ld4(y + idx);
    float yl = (j4 > 0)       ? y[idx - 1] : 0.f;
    float yr = (j4 + 4 < Wd)  ? y[idx + 4] : 0.f;
    Yu.v = (i > 0)      ? ld4(y + idx - Wd) : make_float4(0,0,0,0);
    Yd.v = (i < Hd - 1) ? ld4(y + idx + Wd) : make_float4(0,0,0,0);
    Xd.v = (i == 0)      ? ld4(x + idx + Wd) : make_float4(0,0,0,0);
    Xu.v = (i == Hd - 1) ? ld4(x + idx - Wd) : make_float4(0,0,0,0);

    F4 GX, GY, RC, O1, O2;
#pragma unroll
    for (int k = 0; k < 4; k++) {
        int j = j4 + k;
        float gx;
        if (j == 0)            gx = 0.5f * (X.f[1] - X.f[0]);
        else if (j == Wd - 1)  gx = 0.5f * (X.f[3] - X.f[2]);
        else {
            float yn = (k < 3) ? Y.f[k + 1] : yr;
            float yp = (k > 0) ? Y.f[k - 1] : yl;
            gx = 0.5f * (yn - yp);
        }
        float gy;
        if (i == 0)            gy = 0.5f * (Xd.f[k] - X.f[k]);
        else if (i == Hd - 1)  gy = 0.5f * (X.f[k] - Xu.f[k]);
        else                   gy = 0.5f * (Yd.f[k] - Yu.f[k]);

        float rc = Y.f[k] - X.f[k];
        GX.f[k] = gx; GY.f[k] = gy; RC.f[k] = rc;

        float rho  = rc + EPSf;
        float grad = gx * gx + gy * gy + EPSf;
        float lg   = l_t * grad;
        float v1, v2;
        if      (rho < -lg)   { v1 =  l_t * gx; v2 =  l_t * gy; }
        else if (rho >  lg)   { v1 = -l_t * gx; v2 = -l_t * gy; }
        else if (grad > EPSf) { float s = -rho / grad; v1 = s * gx; v2 = s * gy; }
        else                  { v1 = 0.f; v2 = 0.f; }
        O1.f[k] = v1; O2.f[k] = v2;
    }
    st4(g_g2x + idx, GX.v);
    st4(g_g2y + idx, GY.v);
    st4(g_rc  + idx, RC.v);
    st4(u1 + idx, O1.v);
    st4(u2 + idx, O2.v);
}

// ============================================================================
// P update (per half): forward grads of u, dual projection. In-place p (fp16).
// ============================================================================
template <bool FIRST>
__global__ void __launch_bounds__(256) k_update_p(
    const float* __restrict__ tp, const float* __restrict__ ap,
    const float* __restrict__ u1, const float* __restrict__ u2, int off)
{
    int v = blockIdx.x * blockDim.x + threadIdx.x;
    if (v >= NVH) return;
    int il = v << 2;
    int idx = il + off;
    int j4 = il & (Wd - 1);
    int i  = (il >> 8) & (Hd - 1);

    float taut = ap[0] / tp[0];

    F4 U1, U2, U1d, U2d;
    U1.v = ld4(u1 + idx);
    U2.v = ld4(u2 + idx);
    float u1r = (j4 + 4 < Wd) ? u1[idx + 4] : 0.f;
    float u2r = (j4 + 4 < Wd) ? u2[idx + 4] : 0.f;
    bool has_down = (i < Hd - 1);
    U1d.v = has_down ? ld4(u1 + idx + Wd) : make_float4(0,0,0,0);
    U2d.v = has_down ? ld4(u2 + idx + Wd) : make_float4(0,0,0,0);

    F4 P11, P12, P21, P22;
    if (!FIRST) {
        P11.v = ldh4(g_p11 + idx);
        P12.v = ldh4(g_p12 + idx);
        P21.v = ldh4(g_p21 + idx);
        P22.v = ldh4(g_p22 + idx);
    }

    F4 O11, O12, O21, O22;
#pragma unroll
    for (int k = 0; k < 4; k++) {
        int j = j4 + k;
        float u1x = (j < Wd - 1) ? ((k < 3) ? U1.f[k + 1] : u1r) - U1.f[k] : 0.f;
        float u2x = (j < Wd - 1) ? ((k < 3) ? U2.f[k + 1] : u2r) - U2.f[k] : 0.f;
        float u1y = has_down ? (U1d.f[k] - U1.f[k]) : 0.f;
        float u2y = has_down ? (U2d.f[k] - U2.f[k]) : 0.f;

        float n1 = sqrtf(u1x * u1x + u1y * u1y + EPSf);
        float n2 = sqrtf(u2x * u2x + u2y * u2y + EPSf);
        float f1 = 1.0f / (1.0f + taut * n1);
        float f2 = 1.0f / (1.0f + taut * n2);

        float p11o = FIRST ? 0.f : P11.f[k];
        float p12o = FIRST ? 0.f : P12.f[k];
        float p21o = FIRST ? 0.f : P21.f[k];
        float p22o = FIRST ? 0.f : P22.f[k];

        O11.f[k] = (p11o + taut * u1x) * f1;
        O12.f[k] = (p12o + taut * u1y) * f1;
        O21.f[k] = (p21o + taut * u2x) * f2;
        O22.f[k] = (p22o + taut * u2y) * f2;
    }
    sth4(g_p11 + idx, O11.v);
    sth4(g_p12 + idx, O12.v);
    sth4(g_p21 + idx, O21.v);
    sth4(g_p22 + idx, O22.v);
}

// ============================================================================
// U update (per half): thresholding + u = v + ts * div(p). In-place u.
// ============================================================================
__global__ void __launch_bounds__(256) k_update_u(
    const float* __restrict__ tp, const float* __restrict__ lp,
    float* __restrict__ u1, float* __restrict__ u2, int off)
{
    int v = blockIdx.x * blockDim.x + threadIdx.x;
    if (v >= NVH) return;
    int il = v << 2;
    int idx = il + off;
    int j4 = il & (Wd - 1);
    int i  = (il >> 8) & (Hd - 1);

    float ts  = tp[0];
    float l_t = lp[0] * ts;

    F4 U1, U2, GX, GY, RC, P11, P12, P21, P22, P12u, P22u;
    U1.v  = ld4(u1 + idx);
    U2.v  = ld4(u2 + idx);
    GX.v  = ld4(g_g2x + idx);
    GY.v  = ld4(g_g2y + idx);
    RC.v  = ld4(g_rc + idx);
    P11.v = ldh4(g_p11 + idx);
    P12.v = ldh4(g_p12 + idx);
    P21.v = ldh4(g_p21 + idx);
    P22.v = ldh4(g_p22 + idx);
    float p11l = (j4 > 0) ? __half2float(g_p11[idx - 1]) : 0.f;
    float p21l = (j4 > 0) ? __half2float(g_p21[idx - 1]) : 0.f;
    bool has_up = (i > 0);
    P12u.v = has_up ? ldh4(g_p12 + idx - Wd) : make_float4(0,0,0,0);
    P22u.v = has_up ? ldh4(g_p22 + idx - Wd) : make_float4(0,0,0,0);

    F4 O1, O2;
#pragma unroll
    for (int k = 0; k < 4; k++) {
        int j = j4 + k;
        float lft11 = (k > 0) ? P11.f[k - 1] : p11l;
        float lft21 = (k > 0) ? P21.f[k - 1] : p21l;
        float dx1 = (j == 0) ? P11.f[k] : (P11.f[k] - lft11);
        float dx2 = (j == 0) ? P21.f[k] : (P21.f[k] - lft21);
        float dy1 = has_up ? (P12.f[k] - P12u.f[k]) : P12.f[k];
        float dy2 = has_up ? (P22.f[k] - P22u.f[k]) : P22.f[k];

        float gx = GX.f[k], gy = GY.f[k];
        float rho  = RC.f[k] + gx * U1.f[k] + gy * U2.f[k] + EPSf;
        float grad = gx * gx + gy * gy + EPSf;
        float lg   = l_t * grad;
        float v1, v2;
        if      (rho < -lg)   { v1 =  l_t * gx; v2 =  l_t * gy; }
        else if (rho >  lg)   { v1 = -l_t * gx; v2 = -l_t * gy; }
        else if (grad > EPSf) { float s = -rho / grad; v1 = s * gx; v2 = s * gy; }
        else                  { v1 = 0.f; v2 = 0.f; }

        O1.f[k] = U1.f[k] + v1 + ts * (dx1 + dy1);
        O2.f[k] = U2.f[k] + v2 + ts * (dx2 + dy2);
    }
    st4(u1 + idx, O1.v);
    st4(u2 + idx, O2.v);
}

// ============================================================================
// Launch: full pipeline on batch half 0 (images 0..31), then half 1.
// Per-half working set (u 16MB + p 16MB + g 24MB = 56MB) L2-resident.
// ============================================================================
extern "C" void kernel_launch(void* const* d_in, const int* in_sizes, int n_in,
                              void* d_out, int out_size)
{
    const float* x = (const float*)d_in[0];
    const float* y = (const float*)d_in[1];
    const float* t = (const float*)d_in[8];
    const float* l = (const float*)d_in[9];
    const float* a = (const float*)d_in[10];

    float* u1 = (float*)d_out;
    float* u2 = u1 + NPIX;

    const int threads = 256;
    const int blocks  = (NVH + threads - 1) / threads;

    for (int h = 0; h < 2; ++h) {
        int off = h * HPIX;
        k_init<<<blocks, threads>>>(x, y, t, l, u1, u2, off);
        k_update_p<true><<<blocks, threads>>>(t, a, u1, u2, off);
        for (int it = 0; it < 9; ++it) {
            k_update_u<<<blocks, threads>>>(t, l, u1, u2, off);
            if (it < 8)
                k_update_p<false><<<blocks, threads>>>(t, a, u1, u2, off);
        }
    }
}